// round 4
// baseline (speedup 1.0000x reference)
#include <cuda_runtime.h>
#include <cuda_bf16.h>

// Problem constants (from reference)
#define BB 16
#define NN 4096
#define EE 65536
#define D_IN 128
#define D1 256
#define D2 256
#define D3 128

// Scratch: ping-pong buffers sized for the largest intermediate [B, N, 256]
__device__ float g_bufH[(size_t)BB * NN * 256];
__device__ float g_bufA[(size_t)BB * NN * 256];

// ---------------------------------------------------------------------------
// GEMM: H[M, Nd] = act(X)[M, K] @ W[K, Nd]
// act = ReLU if relu_in, else identity.
// BM=BN=64, BK=16, 256 threads, 4x4 micro-tile per thread.
// M % 64 == 0, K % 16 == 0, Nd % 64 == 0 (holds for all three layers).
// ---------------------------------------------------------------------------
#define BM 64
#define BN 64
#define BK 16

__global__ __launch_bounds__(256) void gemm_kernel(
    const float* __restrict__ X, const float* __restrict__ W,
    float* __restrict__ H, int M, int K, int Nd, int relu_in)
{
    __shared__ float sA[BK][BM + 1];   // +1 pad: conflict-free transposed stores
    __shared__ float sB[BK][BN];

    const int tid = threadIdx.x;
    const int tx = tid & 15;           // 0..15 -> column group
    const int ty = tid >> 4;           // 0..15 -> row group
    const long rowBase = (long)blockIdx.y * BM;
    const int  colBase = blockIdx.x * BN;

    float acc[4][4] = {};

    // A-load mapping: thread t loads float4 at X[rowBase + t/4][k0 + (t%4)*4]
    const int aRow = tid >> 2;         // 0..63
    const int aK4  = (tid & 3) << 2;   // 0,4,8,12
    // B-load mapping: thread t loads float4 at W[k0 + t/16][colBase + (t%16)*4]
    const int bRow = tid >> 4;         // 0..15
    const int bCol = (tid & 15) << 2;  // 0..60

    for (int k0 = 0; k0 < K; k0 += BK) {
        // Load A tile (transposed into sA[k][m]) with optional input ReLU
        float4 av = *(const float4*)(X + (rowBase + aRow) * K + k0 + aK4);
        if (relu_in) {
            av.x = fmaxf(av.x, 0.f); av.y = fmaxf(av.y, 0.f);
            av.z = fmaxf(av.z, 0.f); av.w = fmaxf(av.w, 0.f);
        }
        sA[aK4 + 0][aRow] = av.x;
        sA[aK4 + 1][aRow] = av.y;
        sA[aK4 + 2][aRow] = av.z;
        sA[aK4 + 3][aRow] = av.w;

        // Load B tile
        *(float4*)&sB[bRow][bCol] =
            *(const float4*)(W + (size_t)(k0 + bRow) * Nd + colBase + bCol);

        __syncthreads();

        #pragma unroll
        for (int k = 0; k < BK; k++) {
            float a[4], b[4];
            #pragma unroll
            for (int i = 0; i < 4; i++) a[i] = sA[k][ty * 4 + i];
            #pragma unroll
            for (int j = 0; j < 4; j++) b[j] = sB[k][tx * 4 + j];
            #pragma unroll
            for (int i = 0; i < 4; i++)
                #pragma unroll
                for (int j = 0; j < 4; j++)
                    acc[i][j] = fmaf(a[i], b[j], acc[i][j]);
        }
        __syncthreads();
    }

    #pragma unroll
    for (int i = 0; i < 4; i++) {
        float4 o = make_float4(acc[i][0], acc[i][1], acc[i][2], acc[i][3]);
        *(float4*)(H + (rowBase + ty * 4 + i) * Nd + colBase + tx * 4) = o;
    }
}

// ---------------------------------------------------------------------------
// Init agg: agg[row, :] = valid(row) ? bias : 0
// One float4 per thread.
// ---------------------------------------------------------------------------
__global__ void init_kernel(float* __restrict__ agg, const float* __restrict__ bias,
                            const int* __restrict__ mask, int dout)
{
    const int per_row = dout >> 2;                 // float4s per row
    long idx = (long)blockIdx.x * blockDim.x + threadIdx.x;
    long total = (long)BB * NN * per_row;
    if (idx >= total) return;
    int row = (int)(idx / per_row);
    int c4  = (int)(idx % per_row);
    float4 o;
    if (mask[row] > 0) {
        o = ((const float4*)bias)[c4];
    } else {
        o = make_float4(0.f, 0.f, 0.f, 0.f);
    }
    ((float4*)agg)[idx] = o;
}

// ---------------------------------------------------------------------------
// Scatter: for each valid edge (u -> v): agg[b, v, :] += w * H[b, u, :]
// One warp per edge; lane i handles float4 chunk(s) i, i+32, ...
// ---------------------------------------------------------------------------
__global__ __launch_bounds__(256) void scatter_kernel(
    const float* __restrict__ H, const int* __restrict__ ei,
    const float* __restrict__ ew, const int* __restrict__ mask,
    float* __restrict__ agg, int dout)
{
    const long gwarp = ((long)blockIdx.x * blockDim.x + threadIdx.x) >> 5;
    const int lane = threadIdx.x & 31;
    if (gwarp >= (long)BB * EE) return;
    const int b = (int)(gwarp >> 16);      // E = 65536
    const int e = (int)(gwarp & (EE - 1));

    const int u = ei[((size_t)b * 2) * EE + e];
    const int v = ei[((size_t)b * 2 + 1) * EE + e];
    if (mask[b * NN + u] <= 0 || mask[b * NN + v] <= 0) return;
    const float w = ew[(size_t)b * EE + e];

    const float4* hs = (const float4*)(H + ((size_t)b * NN + u) * dout);
    float* ad = agg + ((size_t)b * NN + v) * dout;

    const int n4 = dout >> 2;
    for (int i = lane; i < n4; i += 32) {
        float4 hv = hs[i];
        atomicAdd(ad + 4 * i + 0, w * hv.x);
        atomicAdd(ad + 4 * i + 1, w * hv.y);
        atomicAdd(ad + 4 * i + 2, w * hv.z);
        atomicAdd(ad + 4 * i + 3, w * hv.w);
    }
}

// ---------------------------------------------------------------------------
// Final ReLU in place on d_out
// ---------------------------------------------------------------------------
__global__ void relu_kernel(float* __restrict__ p, long n4)
{
    long idx = (long)blockIdx.x * blockDim.x + threadIdx.x;
    if (idx >= n4) return;
    float4 v = ((float4*)p)[idx];
    v.x = fmaxf(v.x, 0.f); v.y = fmaxf(v.y, 0.f);
    v.z = fmaxf(v.z, 0.f); v.w = fmaxf(v.w, 0.f);
    ((float4*)p)[idx] = v;
}

// ---------------------------------------------------------------------------
extern "C" void kernel_launch(void* const* d_in, const int* in_sizes, int n_in,
                              void* d_out, int out_size)
{
    const float* x    = (const float*)d_in[0];  // [B, N, 128]
    const int*   ei   = (const int*)  d_in[1];  // [B, 2, E]
    const float* ew   = (const float*)d_in[2];  // [B, E]
    const int*   mask = (const int*)  d_in[3];  // [B, N]
    const float* W1   = (const float*)d_in[4];
    const float* b1   = (const float*)d_in[5];
    const float* W2   = (const float*)d_in[6];
    const float* b2   = (const float*)d_in[7];
    const float* W3   = (const float*)d_in[8];
    const float* b3   = (const float*)d_in[9];
    float* out = (float*)d_out;                  // [B, N, 128]

    float* bufH;
    float* bufA;
    cudaGetSymbolAddress((void**)&bufH, g_bufH);
    cudaGetSymbolAddress((void**)&bufA, g_bufA);

    const int M = BB * NN;                       // 65536

    const int nwarps = BB * EE;                  // 1,048,576 edges/warps
    const int scat_blocks = nwarps / 8;          // 256 threads = 8 warps/block

    // ---- Layer 1: h = x @ W1 ; agg = bias-init + scatter ----
    {
        dim3 grid(D1 / BN, M / BM);
        gemm_kernel<<<grid, 256>>>(x, W1, bufH, M, D_IN, D1, 0);
        long tot4 = (long)M * (D1 / 4);
        init_kernel<<<(int)((tot4 + 255) / 256), 256>>>(bufA, b1, mask, D1);
        scatter_kernel<<<scat_blocks, 256>>>(bufH, ei, ew, mask, bufA, D1);
    }
    // ---- Layer 2: h = relu(agg1) @ W2 ; agg ----
    {
        dim3 grid(D2 / BN, M / BM);
        gemm_kernel<<<grid, 256>>>(bufA, W2, bufH, M, D1, D2, 1);
        // NOTE: bufA is both GEMM input and next agg target -> write agg into bufA
        // only after GEMM consumed it. GEMM finishes before init (same stream). OK.
        long tot4 = (long)M * (D2 / 4);
        init_kernel<<<(int)((tot4 + 255) / 256), 256>>>(bufA, b2, mask, D2);
        scatter_kernel<<<scat_blocks, 256>>>(bufH, ei, ew, mask, bufA, D2);
    }
    // ---- Layer 3: h = relu(agg2) @ W3 ; agg -> d_out ; final relu ----
    {
        dim3 grid(D3 / BN, M / BM);
        gemm_kernel<<<grid, 256>>>(bufA, W3, bufH, M, D2, D3, 1);
        long tot4 = (long)M * (D3 / 4);
        init_kernel<<<(int)((tot4 + 255) / 256), 256>>>(out, b3, mask, D3);
        scatter_kernel<<<scat_blocks, 256>>>(bufH, ei, ew, mask, out, D3);
        relu_kernel<<<(int)((tot4 + 255) / 256), 256>>>(out, tot4);
    }
}